// round 10
// baseline (speedup 1.0000x reference)
#include <cuda_runtime.h>
#include <cuda_bf16.h>
#include <math.h>

#define BB 2
#define SS 2048
#define HH 16
#define DHD 128
#define HIDD 2048
#define NQKV 6144   // (H + 2*HKV) * DH

// ---------------- scratch (static device allocations — allowed) ----------------
__device__ float g_qkv[(size_t)BB * SS * NQKV];         // [4096, 6144]
__device__ float g_q[(size_t)BB * HH * SS * DHD];       // [bh, s, d] RNA-tf32, pre-scaled 1/sqrt(DH)
__device__ float g_k[(size_t)BB * HH * SS * DHD];       // RNA-tf32
__device__ float g_v[(size_t)BB * HH * SS * DHD];       // RNA-tf32
__device__ float g_attn[(size_t)BB * SS * HH * DHD];    // [b, s, h, d] == [4096, 2048]
__device__ float g_hid_r[(size_t)BB * SS * HIDD];       // RNA-tf32-rounded copies
__device__ float g_wqkv_r[(size_t)NQKV * HIDD];
__device__ float g_wo_r[(size_t)HIDD * HIDD];

// ---------------- helpers ----------------
__device__ __forceinline__ unsigned f2tf(float f) {
    unsigned u;
    asm("cvt.rna.tf32.f32 %0, %1;" : "=r"(u) : "f"(f));
    return u;
}

__device__ __forceinline__ unsigned smem_u32(const void* p) {
    unsigned a;
    asm("{ .reg .u64 t; cvta.to.shared.u64 t, %1; cvt.u32.u64 %0, t; }" : "=r"(a) : "l"(p));
    return a;
}

__device__ __forceinline__ void cp16(unsigned dst, const void* src) {
    asm volatile("cp.async.cg.shared.global [%0], [%1], 16;\n" :: "r"(dst), "l"(src));
}

__device__ __forceinline__ void mma_tf32(float (&c)[4],
                                         unsigned a0, unsigned a1, unsigned a2, unsigned a3,
                                         unsigned b0, unsigned b1) {
    asm volatile(
        "mma.sync.aligned.m16n8k8.row.col.f32.tf32.tf32.f32 "
        "{%0,%1,%2,%3},{%4,%5,%6,%7},{%8,%9},{%0,%1,%2,%3};\n"
        : "+f"(c[0]), "+f"(c[1]), "+f"(c[2]), "+f"(c[3])
        : "r"(a0), "r"(a1), "r"(a2), "r"(a3), "r"(b0), "r"(b1));
}

// ---------------- GEMM: unchanged from R9 (measured best: 58% tensor) ------------
#define NSTG 3
#define SRD 36
#define STW (256 * SRD)
#define GEMM_SMEM (NSTG * STW * 4)         // 110592 bytes

__global__ __launch_bounds__(128, 2) void gemm_nt(const float* __restrict__ A,
                                                  const float* __restrict__ Bm,
                                                  float* __restrict__ C,
                                                  int M, int N, int K) {
    extern __shared__ float sm[];
    const unsigned smb = smem_u32(sm);
    const int tid = threadIdx.x;
    const int lane = tid & 31;
    const int w = tid >> 5;
    const int g = lane >> 2;
    const int tg = lane & 3;
    const int wrow = (w >> 1) * 64;
    const int wcol = (w & 1) * 64;
    const int bm = blockIdx.y * 128;
    const int bn = blockIdx.x * 128;
    const int nk = K >> 5;

    float acc[4][8][4];
#pragma unroll
    for (int i = 0; i < 4; i++)
#pragma unroll
        for (int j = 0; j < 8; j++)
#pragma unroll
            for (int l = 0; l < 4; l++) acc[i][j][l] = 0.f;

#define FILL(slot, ktv)                                                                     \
    {                                                                                       \
        const unsigned stA = smb + (slot) * (STW * 4);                                      \
        const unsigned stB = stA + 128 * SRD * 4;                                           \
        const int kof = (ktv) * 32;                                                         \
        _Pragma("unroll")                                                                   \
        for (int i = 0; i < 8; i++) {                                                       \
            int id = tid + 128 * i;                                                         \
            int r = id >> 3, ch = id & 7;                                                   \
            cp16(stA + (r * SRD + ch * 4) * 4, A + (size_t)(bm + r) * K + kof + ch * 4);    \
            cp16(stB + (r * SRD + ch * 4) * 4, Bm + (size_t)(bn + r) * K + kof + ch * 4);   \
        }                                                                                   \
        asm volatile("cp.async.commit_group;" ::: "memory");                                \
    }

    FILL(0, 0)
    FILL(1, 1)

    for (int kt = 0; kt < nk; kt++) {
        asm volatile("cp.async.wait_group 1;" ::: "memory");
        __syncthreads();
        const int pf = kt + 2;
        if (pf < nk) {
            FILL(pf % 3, pf)
        } else {
            asm volatile("cp.async.commit_group;" ::: "memory");
        }

        const float* sa = sm + (kt % 3) * STW;
        const float* sb = sa + 128 * SRD;

        unsigned af[2][4][4], bf[2][8][2];
#define LOAD_FRAGS(p, ks)                                                        \
        {                                                                        \
            const int ko = (ks) * 8 + tg;                                        \
            _Pragma("unroll")                                                    \
            for (int mt = 0; mt < 4; mt++) {                                     \
                int r0 = wrow + mt * 16 + g;                                     \
                af[p][mt][0] = __float_as_uint(sa[r0 * SRD + ko]);               \
                af[p][mt][1] = __float_as_uint(sa[(r0 + 8) * SRD + ko]);         \
                af[p][mt][2] = __float_as_uint(sa[r0 * SRD + ko + 4]);           \
                af[p][mt][3] = __float_as_uint(sa[(r0 + 8) * SRD + ko + 4]);     \
            }                                                                    \
            _Pragma("unroll")                                                    \
            for (int nt = 0; nt < 8; nt++) {                                     \
                int rn = wcol + nt * 8 + g;                                      \
                bf[p][nt][0] = __float_as_uint(sb[rn * SRD + ko]);               \
                bf[p][nt][1] = __float_as_uint(sb[rn * SRD + ko + 4]);           \
            }                                                                    \
        }

        LOAD_FRAGS(0, 0)
#pragma unroll
        for (int ks = 0; ks < 4; ks++) {
            const int cb = ks & 1;
            if (ks < 3) LOAD_FRAGS(cb ^ 1, ks + 1)
#pragma unroll
            for (int mt = 0; mt < 4; mt++)
#pragma unroll
                for (int nt = 0; nt < 8; nt++)
                    mma_tf32(acc[mt][nt], af[cb][mt][0], af[cb][mt][1], af[cb][mt][2],
                             af[cb][mt][3], bf[cb][nt][0], bf[cb][nt][1]);
        }
#undef LOAD_FRAGS
    }

#pragma unroll
    for (int mt = 0; mt < 4; mt++) {
        int rr = bm + wrow + mt * 16 + g;
#pragma unroll
        for (int nt = 0; nt < 8; nt++) {
            int cc = bn + wcol + nt * 8 + 2 * tg;
            *(float2*)&C[(size_t)rr * N + cc] = make_float2(acc[mt][nt][0], acc[mt][nt][1]);
            *(float2*)&C[(size_t)(rr + 8) * N + cc] = make_float2(acc[mt][nt][2], acc[mt][nt][3]);
        }
    }
#undef FILL
}

// ---------------- RNA-tf32 pre-round (elementwise) ----------------
__global__ void round_tf32_kernel(const float4* __restrict__ in, float4* __restrict__ out) {
    int i = blockIdx.x * blockDim.x + threadIdx.x;
    float4 v = in[i];
    v.x = __uint_as_float(f2tf(v.x));
    v.y = __uint_as_float(f2tf(v.y));
    v.z = __uint_as_float(f2tf(v.z));
    v.w = __uint_as_float(f2tf(v.w));
    out[i] = v;
}

// ---------------- RoPE + split + transpose; now writes RNA-tf32-rounded q/k/v ----------
__global__ void rope_split_kernel(const float* __restrict__ cosb, const float* __restrict__ sinb) {
    int idx = blockIdx.x * blockDim.x + threadIdx.x;  // pair index, exact grid
    int m = idx / 3072;
    int p = idx - m * 3072;
    int o = p * 2;
    int head = o >> 7;
    int d = o & 127;
    int b = m >> 11;
    int s = m & 2047;
    float2 x = *(const float2*)(g_qkv + (size_t)m * NQKV + o);
    if (head < 2 * HH) {
        float c = cosb[s * DHD + d];
        float sn = sinb[s * DHD + d];
        float y0 = x.x * c - x.y * sn;
        float y1 = x.y * c + x.x * sn;
        if (head < HH) {
            const float sc = 0.08838834764831845f;  // 1/sqrt(128)
            float* dst = g_q + (((size_t)(b * HH + head)) * SS + s) * DHD + d;
            *(float2*)dst = make_float2(__uint_as_float(f2tf(y0 * sc)),
                                        __uint_as_float(f2tf(y1 * sc)));
        } else {
            float* dst = g_k + (((size_t)(b * HH + head - HH)) * SS + s) * DHD + d;
            *(float2*)dst = make_float2(__uint_as_float(f2tf(y0)), __uint_as_float(f2tf(y1)));
        }
    } else {
        float* dst = g_v + (((size_t)(b * HH + head - 2 * HH)) * SS + s) * DHD + d;
        *(float2*)dst = make_float2(__uint_as_float(f2tf(x.x)), __uint_as_float(f2tf(x.y)));
    }
}

// ---------------- Flash attention: cp.async staged K (double-buffered) + V ----------------
// Grid: (S/128, B*H). 256 threads = 8 warps, each warp owns 16 q-rows.
// smem (words): Q[128*132]=16896 | K 2x[64*132]=16896 | V[64*132]=8448 | P[128*68]=8704
#define FA_SMEM_BYTES 203776

__global__ __launch_bounds__(256, 1) void flash_kernel() {
    extern __shared__ unsigned fsm[];
    unsigned* sQ = fsm;                 // 16896
    unsigned* sKb = fsm + 16896;        // two 8448 buffers
    unsigned* sV = fsm + 33792;         // 8448
    unsigned* sP = fsm + 42240;         // 8704
    const unsigned smb = smem_u32(fsm);

    const int tid = threadIdx.x;
    const int lane = tid & 31;
    const int w = tid >> 5;
    const int g = lane >> 2;
    const int tg = lane & 3;
    const int qt = blockIdx.x;
    const int bh = blockIdx.y;
    const int qrow = w * 16;

    // prologue: Q (group 0), K0 (group 1) via cp.async — values are pre-rounded tf32
    const float* qp = g_q + ((size_t)bh * SS + qt * 128) * DHD;
#pragma unroll
    for (int i = 0; i < 16; i++) {
        int id = tid + 256 * i;
        int r = id >> 5, c4 = (id & 31) * 4;
        cp16(smb + (r * 132 + c4) * 4, qp + (size_t)r * DHD + c4);
    }
    asm volatile("cp.async.commit_group;" ::: "memory");
    {
        const float* kp = g_k + (size_t)bh * SS * DHD;
#pragma unroll
        for (int i = 0; i < 8; i++) {
            int id = tid + 256 * i;
            int r = id >> 5, c4 = (id & 31) * 4;
            cp16(smb + 16896 * 4 + (r * 132 + c4) * 4, kp + (size_t)r * DHD + c4);
        }
        asm volatile("cp.async.commit_group;" ::: "memory");
    }

    float m0 = -1e30f, m1 = -1e30f, l0 = 0.f, l1 = 0.f;
    float oacc[16][4];
#pragma unroll
    for (int nt = 0; nt < 16; nt++) { oacc[nt][0] = 0; oacc[nt][1] = 0; oacc[nt][2] = 0; oacc[nt][3] = 0; }

    for (int kt = 0; kt < SS / 64; kt++) {
        // issue V(kt)
        {
            const float* vp = g_v + ((size_t)bh * SS + kt * 64) * DHD;
#pragma unroll
            for (int i = 0; i < 8; i++) {
                int id = tid + 256 * i;
                int r = id >> 5, c4 = (id & 31) * 4;
                cp16(smb + 33792 * 4 + (r * 132 + c4) * 4, vp + (size_t)r * DHD + c4);
            }
            asm volatile("cp.async.commit_group;" ::: "memory");
        }
        // wait K(kt) (and Q on kt=0); V(kt) may remain in flight
        asm volatile("cp.async.wait_group 1;" ::: "memory");
        __syncthreads();

        const unsigned* sK = sKb + (kt & 1) * 8448;

        // S = Q K^T  (scale folded into Q)
        float sacc[8][4];
#pragma unroll
        for (int nt = 0; nt < 8; nt++) { sacc[nt][0] = 0; sacc[nt][1] = 0; sacc[nt][2] = 0; sacc[nt][3] = 0; }
#pragma unroll
        for (int ks = 0; ks < 16; ks++) {
            unsigned a0 = sQ[(qrow + g) * 132 + ks * 8 + tg];
            unsigned a1 = sQ[(qrow + g + 8) * 132 + ks * 8 + tg];
            unsigned a2 = sQ[(qrow + g) * 132 + ks * 8 + tg + 4];
            unsigned a3 = sQ[(qrow + g + 8) * 132 + ks * 8 + tg + 4];
#pragma unroll
            for (int nt = 0; nt < 8; nt++) {
                unsigned b0 = sK[(nt * 8 + g) * 132 + ks * 8 + tg];
                unsigned b1 = sK[(nt * 8 + g) * 132 + ks * 8 + tg + 4];
                mma_tf32(sacc[nt], a0, a1, a2, a3, b0, b1);
            }
        }

        // prefetch K(kt+1) into the other buffer (safe: consumed buffer differs)
        if (kt + 1 < SS / 64) {
            const float* kp = g_k + ((size_t)bh * SS + (kt + 1) * 64) * DHD;
            const unsigned kdst = smb + (16896 + ((kt + 1) & 1) * 8448) * 4;
#pragma unroll
            for (int i = 0; i < 8; i++) {
                int id = tid + 256 * i;
                int r = id >> 5, c4 = (id & 31) * 4;
                cp16(kdst + (r * 132 + c4) * 4, kp + (size_t)r * DHD + c4);
            }
        }
        asm volatile("cp.async.commit_group;" ::: "memory");

        // online softmax (rows g and g+8 of this warp's 16)
        float mx0 = sacc[0][0], mx1 = sacc[0][2];
#pragma unroll
        for (int nt = 0; nt < 8; nt++) {
            mx0 = fmaxf(mx0, fmaxf(sacc[nt][0], sacc[nt][1]));
            mx1 = fmaxf(mx1, fmaxf(sacc[nt][2], sacc[nt][3]));
        }
        mx0 = fmaxf(mx0, __shfl_xor_sync(0xffffffffu, mx0, 1));
        mx0 = fmaxf(mx0, __shfl_xor_sync(0xffffffffu, mx0, 2));
        mx1 = fmaxf(mx1, __shfl_xor_sync(0xffffffffu, mx1, 1));
        mx1 = fmaxf(mx1, __shfl_xor_sync(0xffffffffu, mx1, 2));
        float nm0 = fmaxf(m0, mx0), nm1 = fmaxf(m1, mx1);
        float al0 = __expf(m0 - nm0), al1 = __expf(m1 - nm1);
        float sum0 = 0.f, sum1 = 0.f;
        unsigned* pr0 = sP + (qrow + g) * 68;
        unsigned* pr1 = sP + (qrow + g + 8) * 68;
#pragma unroll
        for (int nt = 0; nt < 8; nt++) {
            int cc = nt * 8 + 2 * tg;
            unsigned u00 = f2tf(__expf(sacc[nt][0] - nm0));
            unsigned u01 = f2tf(__expf(sacc[nt][1] - nm0));
            unsigned u10 = f2tf(__expf(sacc[nt][2] - nm1));
            unsigned u11 = f2tf(__expf(sacc[nt][3] - nm1));
            sum0 += __uint_as_float(u00) + __uint_as_float(u01);  // sum the tf32-rounded P
            sum1 += __uint_as_float(u10) + __uint_as_float(u11);
            pr0[cc] = u00; pr0[cc + 1] = u01;
            pr1[cc] = u10; pr1[cc + 1] = u11;
        }
        sum0 += __shfl_xor_sync(0xffffffffu, sum0, 1);
        sum0 += __shfl_xor_sync(0xffffffffu, sum0, 2);
        sum1 += __shfl_xor_sync(0xffffffffu, sum1, 1);
        sum1 += __shfl_xor_sync(0xffffffffu, sum1, 2);
        l0 = l0 * al0 + sum0;
        l1 = l1 * al1 + sum1;
        m0 = nm0; m1 = nm1;
#pragma unroll
        for (int nt = 0; nt < 16; nt++) {
            oacc[nt][0] *= al0; oacc[nt][1] *= al0;
            oacc[nt][2] *= al1; oacc[nt][3] *= al1;
        }

        // wait V(kt): FIFO => allowing 1 pending group (K(kt+1)) proves V done;
        // last ktile has no K prefetch group with work, so drain fully.
        if (kt + 1 < SS / 64)
            asm volatile("cp.async.wait_group 1;" ::: "memory");
        else
            asm volatile("cp.async.wait_group 0;" ::: "memory");
        __syncthreads();

        // O += P V
#pragma unroll
        for (int ks = 0; ks < 8; ks++) {
            unsigned a0 = sP[(qrow + g) * 68 + ks * 8 + tg];
            unsigned a1 = sP[(qrow + g + 8) * 68 + ks * 8 + tg];
            unsigned a2 = sP[(qrow + g) * 68 + ks * 8 + tg + 4];
            unsigned a3 = sP[(qrow + g + 8) * 68 + ks * 8 + tg + 4];
#pragma unroll
            for (int nt = 0; nt < 16; nt++) {
                unsigned b0 = sV[(ks * 8 + tg) * 132 + nt * 8 + g];
                unsigned b1 = sV[(ks * 8 + tg + 4) * 132 + nt * 8 + g];
                mma_tf32(oacc[nt], a0, a1, a2, a3, b0, b1);
            }
        }
        __syncthreads();   // protects sP and sV for next ktile
    }

    float inv0 = 1.0f / l0, inv1 = 1.0f / l1;
    int b = bh >> 4, h = bh & 15;
    int srow = qt * 128 + qrow + g;
    float* op0 = g_attn + (((size_t)b * SS + srow) * HH + h) * DHD;
    float* op1 = op0 + (size_t)8 * HH * DHD;
    // outputs written RNA-tf32-rounded: gemm_nt (tf32 mma) then sees exact operands
#pragma unroll
    for (int nt = 0; nt < 16; nt++) {
        int cc = nt * 8 + 2 * tg;
        *(float2*)(op0 + cc) = make_float2(__uint_as_float(f2tf(oacc[nt][0] * inv0)),
                                           __uint_as_float(f2tf(oacc[nt][1] * inv0)));
        *(float2*)(op1 + cc) = make_float2(__uint_as_float(f2tf(oacc[nt][2] * inv1)),
                                           __uint_as_float(f2tf(oacc[nt][3] * inv1)));
    }
}

// ---------------- launcher ----------------
extern "C" void kernel_launch(void* const* d_in, const int* in_sizes, int n_in,
                              void* d_out, int out_size) {
    const float* hidden = (const float*)d_in[0];
    const float* cosb   = (const float*)d_in[1];
    const float* sinb   = (const float*)d_in[2];
    const float* wqkv   = (const float*)d_in[3];
    const float* wo     = (const float*)d_in[4];

    float *qkv = nullptr, *attn = nullptr, *hid_r = nullptr, *wqkv_r = nullptr, *wo_r = nullptr;
    cudaGetSymbolAddress((void**)&qkv, g_qkv);
    cudaGetSymbolAddress((void**)&attn, g_attn);
    cudaGetSymbolAddress((void**)&hid_r, g_hid_r);
    cudaGetSymbolAddress((void**)&wqkv_r, g_wqkv_r);
    cudaGetSymbolAddress((void**)&wo_r, g_wo_r);
    cudaFuncSetAttribute(flash_kernel, cudaFuncAttributeMaxDynamicSharedMemorySize, FA_SMEM_BYTES);
    cudaFuncSetAttribute(gemm_nt, cudaFuncAttributeMaxDynamicSharedMemorySize, GEMM_SMEM);

    // 0) RNA-tf32 pre-round of GEMM operands (exact grids: n/4/256 blocks)
    round_tf32_kernel<<<8192, 256>>>((const float4*)hidden, (float4*)hid_r);     // 8.4M elems
    round_tf32_kernel<<<12288, 256>>>((const float4*)wqkv, (float4*)wqkv_r);     // 12.6M
    round_tf32_kernel<<<4096, 256>>>((const float4*)wo, (float4*)wo_r);          // 4.2M

    // 1) QKV projection: [4096,2048] x [6144,2048]^T
    gemm_nt<<<dim3(NQKV / 128, (BB * SS) / 128), 128, GEMM_SMEM>>>(hid_r, wqkv_r, qkv, BB * SS, NQKV, HIDD);

    // 2) RoPE + split + transpose (writes RNA-tf32-rounded q/k/v)
    rope_split_kernel<<<49152, 256>>>(cosb, sinb);

    // 3) Attention (writes tf32-rounded attn)
    flash_kernel<<<dim3(SS / 128, BB * HH), 256, FA_SMEM_BYTES>>>();

    // 4) Output projection: [4096,2048] x [2048,2048]^T -> d_out
    gemm_nt<<<dim3(HIDD / 128, (BB * SS) / 128), 128, GEMM_SMEM>>>(attn, wo_r, (float*)d_out, BB * SS, HIDD, HIDD);
}

// round 12
// speedup vs baseline: 1.0191x; 1.0191x over previous
#include <cuda_runtime.h>
#include <cuda_bf16.h>
#include <math.h>

#define BB 2
#define SS 2048
#define HH 16
#define DHD 128
#define HIDD 2048
#define NQKV 6144   // (H + 2*HKV) * DH

// ---------------- scratch (static device allocations — allowed) ----------------
__device__ float g_qkv[(size_t)BB * SS * NQKV];         // [4096, 6144]
__device__ float g_q[(size_t)BB * HH * SS * DHD];       // [bh, s, d] RNA-tf32, pre-scaled 1/sqrt(DH)
__device__ float g_k[(size_t)BB * HH * SS * DHD];       // RNA-tf32
__device__ float g_v[(size_t)BB * HH * SS * DHD];       // RNA-tf32
__device__ float g_attn[(size_t)BB * SS * HH * DHD];    // [b, s, h, d] == [4096, 2048]
__device__ float g_hid_r[(size_t)BB * SS * HIDD];       // RNA-tf32-rounded copies
__device__ float g_wqkv_r[(size_t)NQKV * HIDD];
__device__ float g_wo_r[(size_t)HIDD * HIDD];

// ---------------- helpers ----------------
__device__ __forceinline__ unsigned f2tf(float f) {
    unsigned u;
    asm("cvt.rna.tf32.f32 %0, %1;" : "=r"(u) : "f"(f));
    return u;
}

__device__ __forceinline__ unsigned smem_u32(const void* p) {
    unsigned a;
    asm("{ .reg .u64 t; cvta.to.shared.u64 t, %1; cvt.u32.u64 %0, t; }" : "=r"(a) : "l"(p));
    return a;
}

__device__ __forceinline__ void cp16(unsigned dst, const void* src) {
    asm volatile("cp.async.cg.shared.global [%0], [%1], 16;\n" :: "r"(dst), "l"(src));
}

__device__ __forceinline__ void mma_tf32(float (&c)[4],
                                         unsigned a0, unsigned a1, unsigned a2, unsigned a3,
                                         unsigned b0, unsigned b1) {
    asm volatile(
        "mma.sync.aligned.m16n8k8.row.col.f32.tf32.tf32.f32 "
        "{%0,%1,%2,%3},{%4,%5,%6,%7},{%8,%9},{%0,%1,%2,%3};\n"
        : "+f"(c[0]), "+f"(c[1]), "+f"(c[2]), "+f"(c[3])
        : "r"(a0), "r"(a1), "r"(a2), "r"(a3), "r"(b0), "r"(b1));
}

// ---------------- GEMM: unchanged from R9 (measured: 663us GEMM1, 58% tensor) ------------
#define NSTG 3
#define SRD 36
#define STW (256 * SRD)
#define GEMM_SMEM (NSTG * STW * 4)         // 110592 bytes

__global__ __launch_bounds__(128, 2) void gemm_nt(const float* __restrict__ A,
                                                  const float* __restrict__ Bm,
                                                  float* __restrict__ C,
                                                  int M, int N, int K) {
    extern __shared__ float sm[];
    const unsigned smb = smem_u32(sm);
    const int tid = threadIdx.x;
    const int lane = tid & 31;
    const int w = tid >> 5;
    const int g = lane >> 2;
    const int tg = lane & 3;
    const int wrow = (w >> 1) * 64;
    const int wcol = (w & 1) * 64;
    const int bm = blockIdx.y * 128;
    const int bn = blockIdx.x * 128;
    const int nk = K >> 5;

    float acc[4][8][4];
#pragma unroll
    for (int i = 0; i < 4; i++)
#pragma unroll
        for (int j = 0; j < 8; j++)
#pragma unroll
            for (int l = 0; l < 4; l++) acc[i][j][l] = 0.f;

#define FILL(slot, ktv)                                                                     \
    {                                                                                       \
        const unsigned stA = smb + (slot) * (STW * 4);                                      \
        const unsigned stB = stA + 128 * SRD * 4;                                           \
        const int kof = (ktv) * 32;                                                         \
        _Pragma("unroll")                                                                   \
        for (int i = 0; i < 8; i++) {                                                       \
            int id = tid + 128 * i;                                                         \
            int r = id >> 3, ch = id & 7;                                                   \
            cp16(stA + (r * SRD + ch * 4) * 4, A + (size_t)(bm + r) * K + kof + ch * 4);    \
            cp16(stB + (r * SRD + ch * 4) * 4, Bm + (size_t)(bn + r) * K + kof + ch * 4);   \
        }                                                                                   \
        asm volatile("cp.async.commit_group;" ::: "memory");                                \
    }

    FILL(0, 0)
    FILL(1, 1)

    for (int kt = 0; kt < nk; kt++) {
        asm volatile("cp.async.wait_group 1;" ::: "memory");
        __syncthreads();
        const int pf = kt + 2;
        if (pf < nk) {
            FILL(pf % 3, pf)
        } else {
            asm volatile("cp.async.commit_group;" ::: "memory");
        }

        const float* sa = sm + (kt % 3) * STW;
        const float* sb = sa + 128 * SRD;

        unsigned af[2][4][4], bf[2][8][2];
#define LOAD_FRAGS(p, ks)                                                        \
        {                                                                        \
            const int ko = (ks) * 8 + tg;                                        \
            _Pragma("unroll")                                                    \
            for (int mt = 0; mt < 4; mt++) {                                     \
                int r0 = wrow + mt * 16 + g;                                     \
                af[p][mt][0] = __float_as_uint(sa[r0 * SRD + ko]);               \
                af[p][mt][1] = __float_as_uint(sa[(r0 + 8) * SRD + ko]);         \
                af[p][mt][2] = __float_as_uint(sa[r0 * SRD + ko + 4]);           \
                af[p][mt][3] = __float_as_uint(sa[(r0 + 8) * SRD + ko + 4]);     \
            }                                                                    \
            _Pragma("unroll")                                                    \
            for (int nt = 0; nt < 8; nt++) {                                     \
                int rn = wcol + nt * 8 + g;                                      \
                bf[p][nt][0] = __float_as_uint(sb[rn * SRD + ko]);               \
                bf[p][nt][1] = __float_as_uint(sb[rn * SRD + ko + 4]);           \
            }                                                                    \
        }

        LOAD_FRAGS(0, 0)
#pragma unroll
        for (int ks = 0; ks < 4; ks++) {
            const int cb = ks & 1;
            if (ks < 3) LOAD_FRAGS(cb ^ 1, ks + 1)
#pragma unroll
            for (int mt = 0; mt < 4; mt++)
#pragma unroll
                for (int nt = 0; nt < 8; nt++)
                    mma_tf32(acc[mt][nt], af[cb][mt][0], af[cb][mt][1], af[cb][mt][2],
                             af[cb][mt][3], bf[cb][nt][0], bf[cb][nt][1]);
        }
#undef LOAD_FRAGS
    }

#pragma unroll
    for (int mt = 0; mt < 4; mt++) {
        int rr = bm + wrow + mt * 16 + g;
#pragma unroll
        for (int nt = 0; nt < 8; nt++) {
            int cc = bn + wcol + nt * 8 + 2 * tg;
            *(float2*)&C[(size_t)rr * N + cc] = make_float2(acc[mt][nt][0], acc[mt][nt][1]);
            *(float2*)&C[(size_t)(rr + 8) * N + cc] = make_float2(acc[mt][nt][2], acc[mt][nt][3]);
        }
    }
#undef FILL
}

// ---------------- RNA-tf32 pre-round (elementwise) ----------------
__global__ void round_tf32_kernel(const float4* __restrict__ in, float4* __restrict__ out) {
    int i = blockIdx.x * blockDim.x + threadIdx.x;
    float4 v = in[i];
    v.x = __uint_as_float(f2tf(v.x));
    v.y = __uint_as_float(f2tf(v.y));
    v.z = __uint_as_float(f2tf(v.z));
    v.w = __uint_as_float(f2tf(v.w));
    out[i] = v;
}

// ---------------- RoPE + split + transpose; writes RNA-tf32-rounded q/k/v ----------
__global__ void rope_split_kernel(const float* __restrict__ cosb, const float* __restrict__ sinb) {
    int idx = blockIdx.x * blockDim.x + threadIdx.x;  // pair index, exact grid
    int m = idx / 3072;
    int p = idx - m * 3072;
    int o = p * 2;
    int head = o >> 7;
    int d = o & 127;
    int b = m >> 11;
    int s = m & 2047;
    float2 x = *(const float2*)(g_qkv + (size_t)m * NQKV + o);
    if (head < 2 * HH) {
        float c = cosb[s * DHD + d];
        float sn = sinb[s * DHD + d];
        float y0 = x.x * c - x.y * sn;
        float y1 = x.y * c + x.x * sn;
        if (head < HH) {
            const float sc = 0.08838834764831845f;  // 1/sqrt(128)
            float* dst = g_q + (((size_t)(b * HH + head)) * SS + s) * DHD + d;
            *(float2*)dst = make_float2(__uint_as_float(f2tf(y0 * sc)),
                                        __uint_as_float(f2tf(y1 * sc)));
        } else {
            float* dst = g_k + (((size_t)(b * HH + head - HH)) * SS + s) * DHD + d;
            *(float2*)dst = make_float2(__uint_as_float(f2tf(y0)), __uint_as_float(f2tf(y1)));
        }
    } else {
        float* dst = g_v + (((size_t)(b * HH + head - 2 * HH)) * SS + s) * DHD + d;
        *(float2*)dst = make_float2(__uint_as_float(f2tf(x.x)), __uint_as_float(f2tf(x.y)));
    }
}

// ---------------- Flash attention: Q in registers, K+V double-buffered cp.async ----------
// Grid: (S/128, B*H). 256 threads = 8 warps, each warp owns 16 q-rows.
// smem (words): K 2x[64*132] @0 | V 2x[64*132] @16896 | P [128*68] @33792  -> 169984 B
// Q is staged once through the K-buffer region, loaded to 64 regs/thread, region reused.
// One {K,V} cp.async group per ktile; ONE wait + ONE __syncthreads per ktile.
#define FA_SMEM_BYTES 169984

__global__ __launch_bounds__(256, 1) void flash_kernel() {
    extern __shared__ unsigned fsm[];
    unsigned* sP = fsm + 33792;
    const unsigned smb = smem_u32(fsm);

    const int tid = threadIdx.x;
    const int lane = tid & 31;
    const int w = tid >> 5;
    const int g = lane >> 2;
    const int tg = lane & 3;
    const int qt = blockIdx.x;
    const int bh = blockIdx.y;
    const int qrow = w * 16;

    // ---- stage Q through smem once, load A-fragments into registers ----
    {
        const float* qp = g_q + ((size_t)bh * SS + qt * 128) * DHD;
#pragma unroll
        for (int i = 0; i < 16; i++) {
            int id = tid + 256 * i;
            int r = id >> 5, c4 = (id & 31) * 4;
            cp16(smb + (r * 132 + c4) * 4, qp + (size_t)r * DHD + c4);
        }
        asm volatile("cp.async.commit_group;" ::: "memory");
        asm volatile("cp.async.wait_group 0;" ::: "memory");
        __syncthreads();
    }
    unsigned qf[16][4];
#pragma unroll
    for (int ks = 0; ks < 16; ks++) {
        int ko = ks * 8 + tg;
        qf[ks][0] = fsm[(qrow + g) * 132 + ko];
        qf[ks][1] = fsm[(qrow + g + 8) * 132 + ko];
        qf[ks][2] = fsm[(qrow + g) * 132 + ko + 4];
        qf[ks][3] = fsm[(qrow + g + 8) * 132 + ko + 4];
    }
    __syncthreads();   // all Q reads done before K0/V0 overwrite the region

    // ---- issue group G0 = {K0, V0} ----
    {
        const float* kp = g_k + (size_t)bh * SS * DHD;
        const float* vp = g_v + (size_t)bh * SS * DHD;
#pragma unroll
        for (int i = 0; i < 8; i++) {
            int id = tid + 256 * i;
            int r = id >> 5, c4 = (id & 31) * 4;
            cp16(smb + (r * 132 + c4) * 4, kp + (size_t)r * DHD + c4);
            cp16(smb + (16896 + r * 132 + c4) * 4, vp + (size_t)r * DHD + c4);
        }
        asm volatile("cp.async.commit_group;" ::: "memory");
    }

    float m0 = -1e30f, m1 = -1e30f, l0 = 0.f, l1 = 0.f;
    float oacc[16][4];
#pragma unroll
    for (int nt = 0; nt < 16; nt++) { oacc[nt][0] = 0; oacc[nt][1] = 0; oacc[nt][2] = 0; oacc[nt][3] = 0; }

    for (int kt = 0; kt < SS / 64; kt++) {
        // the ONLY wait+barrier of the ktile: G(kt) = {K(kt), V(kt)} landed
        asm volatile("cp.async.wait_group 0;" ::: "memory");
        __syncthreads();

        const unsigned* sK = fsm + (kt & 1) * 8448;
        const unsigned* sV = fsm + 16896 + (kt & 1) * 8448;

        // S = Q K^T  (Q fragments in registers; scale folded into Q)
        float sacc[8][4];
#pragma unroll
        for (int nt = 0; nt < 8; nt++) { sacc[nt][0] = 0; sacc[nt][1] = 0; sacc[nt][2] = 0; sacc[nt][3] = 0; }
#pragma unroll
        for (int ks = 0; ks < 16; ks++) {
            const int ko = ks * 8 + tg;
#pragma unroll
            for (int nt = 0; nt < 8; nt++) {
                unsigned b0 = sK[(nt * 8 + g) * 132 + ko];
                unsigned b1 = sK[(nt * 8 + g) * 132 + ko + 4];
                mma_tf32(sacc[nt], qf[ks][0], qf[ks][1], qf[ks][2], qf[ks][3], b0, b1);
            }
        }

        // prefetch G(kt+1) = {K(kt+1), V(kt+1)} into the other buffers.
        // Safe: those buffers' last readers (iteration kt-1) all passed this
        // iteration's __syncthreads before any thread reaches this point.
        if (kt + 1 < SS / 64) {
            const float* kp = g_k + ((size_t)bh * SS + (kt + 1) * 64) * DHD;
            const float* vp = g_v + ((size_t)bh * SS + (kt + 1) * 64) * DHD;
            const unsigned kdst = smb + (((kt + 1) & 1) * 8448) * 4;
            const unsigned vdst = smb + ((16896 + ((kt + 1) & 1) * 8448)) * 4;
#pragma unroll
            for (int i = 0; i < 8; i++) {
                int id = tid + 256 * i;
                int r = id >> 5, c4 = (id & 31) * 4;
                cp16(kdst + (r * 132 + c4) * 4, kp + (size_t)r * DHD + c4);
                cp16(vdst + (r * 132 + c4) * 4, vp + (size_t)r * DHD + c4);
            }
            asm volatile("cp.async.commit_group;" ::: "memory");
        }

        // online softmax (rows g and g+8 of this warp's 16)
        float mx0 = sacc[0][0], mx1 = sacc[0][2];
#pragma unroll
        for (int nt = 0; nt < 8; nt++) {
            mx0 = fmaxf(mx0, fmaxf(sacc[nt][0], sacc[nt][1]));
            mx1 = fmaxf(mx1, fmaxf(sacc[nt][2], sacc[nt][3]));
        }
        mx0 = fmaxf(mx0, __shfl_xor_sync(0xffffffffu, mx0, 1));
        mx0 = fmaxf(mx0, __shfl_xor_sync(0xffffffffu, mx0, 2));
        mx1 = fmaxf(mx1, __shfl_xor_sync(0xffffffffu, mx1, 1));
        mx1 = fmaxf(mx1, __shfl_xor_sync(0xffffffffu, mx1, 2));
        float nm0 = fmaxf(m0, mx0), nm1 = fmaxf(m1, mx1);
        float al0 = __expf(m0 - nm0), al1 = __expf(m1 - nm1);
        float sum0 = 0.f, sum1 = 0.f;
        unsigned* pr0 = sP + (qrow + g) * 68;
        unsigned* pr1 = sP + (qrow + g + 8) * 68;
#pragma unroll
        for (int nt = 0; nt < 8; nt++) {
            int cc = nt * 8 + 2 * tg;
            unsigned u00 = f2tf(__expf(sacc[nt][0] - nm0));
            unsigned u01 = f2tf(__expf(sacc[nt][1] - nm0));
            unsigned u10 = f2tf(__expf(sacc[nt][2] - nm1));
            unsigned u11 = f2tf(__expf(sacc[nt][3] - nm1));
            sum0 += __uint_as_float(u00) + __uint_as_float(u01);  // sum the tf32-rounded P
            sum1 += __uint_as_float(u10) + __uint_as_float(u11);
            pr0[cc] = u00; pr0[cc + 1] = u01;
            pr1[cc] = u10; pr1[cc + 1] = u11;
        }
        sum0 += __shfl_xor_sync(0xffffffffu, sum0, 1);
        sum0 += __shfl_xor_sync(0xffffffffu, sum0, 2);
        sum1 += __shfl_xor_sync(0xffffffffu, sum1, 1);
        sum1 += __shfl_xor_sync(0xffffffffu, sum1, 2);
        l0 = l0 * al0 + sum0;
        l1 = l1 * al1 + sum1;
        m0 = nm0; m1 = nm1;
#pragma unroll
        for (int nt = 0; nt < 16; nt++) {
            oacc[nt][0] *= al0; oacc[nt][1] *= al0;
            oacc[nt][2] *= al1; oacc[nt][3] *= al1;
        }
        __syncwarp();   // sP is warp-private: cross-lane visibility only

        // O += P V
#pragma unroll
        for (int ks = 0; ks < 8; ks++) {
            unsigned a0 = sP[(qrow + g) * 68 + ks * 8 + tg];
            unsigned a1 = sP[(qrow + g + 8) * 68 + ks * 8 + tg];
            unsigned a2 = sP[(qrow + g) * 68 + ks * 8 + tg + 4];
            unsigned a3 = sP[(qrow + g + 8) * 68 + ks * 8 + tg + 4];
#pragma unroll
            for (int nt = 0; nt < 16; nt++) {
                unsigned b0 = sV[(ks * 8 + tg) * 132 + nt * 8 + g];
                unsigned b1 = sV[(ks * 8 + tg + 4) * 132 + nt * 8 + g];
                mma_tf32(oacc[nt], a0, a1, a2, a3, b0, b1);
            }
        }
    }

    float inv0 = 1.0f / l0, inv1 = 1.0f / l1;
    int b = bh >> 4, h = bh & 15;
    int srow = qt * 128 + qrow + g;
    float* op0 = g_attn + (((size_t)b * SS + srow) * HH + h) * DHD;
    float* op1 = op0 + (size_t)8 * HH * DHD;
    // outputs written RNA-tf32-rounded: gemm_nt (tf32 mma) then sees exact operands
#pragma unroll
    for (int nt = 0; nt < 16; nt++) {
        int cc = nt * 8 + 2 * tg;
        *(float2*)(op0 + cc) = make_float2(__uint_as_float(f2tf(oacc[nt][0] * inv0)),
                                           __uint_as_float(f2tf(oacc[nt][1] * inv0)));
        *(float2*)(op1 + cc) = make_float2(__uint_as_float(f2tf(oacc[nt][2] * inv1)),
                                           __uint_as_float(f2tf(oacc[nt][3] * inv1)));
    }
}

// ---------------- launcher ----------------
extern "C" void kernel_launch(void* const* d_in, const int* in_sizes, int n_in,
                              void* d_out, int out_size) {
    const float* hidden = (const float*)d_in[0];
    const float* cosb   = (const float*)d_in[1];
    const float* sinb   = (const float*)d_in[2];
    const float* wqkv   = (const float*)d_in[3];
    const float* wo     = (const float*)d_in[4];

    float *qkv = nullptr, *attn = nullptr, *hid_r = nullptr, *wqkv_r = nullptr, *wo_r = nullptr;
    cudaGetSymbolAddress((void**)&qkv, g_qkv);
    cudaGetSymbolAddress((void**)&attn, g_attn);
    cudaGetSymbolAddress((void**)&hid_r, g_hid_r);
    cudaGetSymbolAddress((void**)&wqkv_r, g_wqkv_r);
    cudaGetSymbolAddress((void**)&wo_r, g_wo_r);
    cudaFuncSetAttribute(flash_kernel, cudaFuncAttributeMaxDynamicSharedMemorySize, FA_SMEM_BYTES);
    cudaFuncSetAttribute(gemm_nt, cudaFuncAttributeMaxDynamicSharedMemorySize, GEMM_SMEM);

    // 0) RNA-tf32 pre-round of GEMM operands (exact grids: n/4/256 blocks)
    round_tf32_kernel<<<8192, 256>>>((const float4*)hidden, (float4*)hid_r);     // 8.4M elems
    round_tf32_kernel<<<12288, 256>>>((const float4*)wqkv, (float4*)wqkv_r);     // 12.6M
    round_tf32_kernel<<<4096, 256>>>((const float4*)wo, (float4*)wo_r);          // 4.2M

    // 1) QKV projection: [4096,2048] x [6144,2048]^T
    gemm_nt<<<dim3(NQKV / 128, (BB * SS) / 128), 128, GEMM_SMEM>>>(hid_r, wqkv_r, qkv, BB * SS, NQKV, HIDD);

    // 2) RoPE + split + transpose (writes RNA-tf32-rounded q/k/v)
    rope_split_kernel<<<49152, 256>>>(cosb, sinb);

    // 3) Attention (writes tf32-rounded attn)
    flash_kernel<<<dim3(SS / 128, BB * HH), 256, FA_SMEM_BYTES>>>();

    // 4) Output projection: [4096,2048] x [2048,2048]^T -> d_out
    gemm_nt<<<dim3(HIDD / 128, (BB * SS) / 128), 128, GEMM_SMEM>>>(attn, wo_r, (float*)d_out, BB * SS, HIDD, HIDD);
}

// round 15
// speedup vs baseline: 1.4090x; 1.3826x over previous
#include <cuda_runtime.h>
#include <cuda_fp16.h>
#include <math.h>

#define BB 2
#define SS 2048
#define HH 16
#define DHD 128
#define HIDD 2048
#define NQKV 6144   // (H + 2*HKV) * DH

// ---------------- scratch (static device allocations — allowed) ----------------
__device__ float g_qkv[(size_t)BB * SS * NQKV];         // [4096, 6144] fp32 (GEMM1 out)
__device__ float g_q[(size_t)BB * HH * SS * DHD];       // [bh, s, d] fp32 (scale folded)
__device__ float g_k[(size_t)BB * HH * SS * DHD];
__device__ float g_v[(size_t)BB * HH * SS * DHD];
__device__ __half g_attn_h[(size_t)BB * SS * HH * DHD]; // [b, s, h, d] fp16 (GEMM2 A)
__device__ __half g_hid_h[(size_t)BB * SS * HIDD];      // fp16 copies of GEMM operands
__device__ __half g_wqkv_h[(size_t)NQKV * HIDD];
__device__ __half g_wo_h[(size_t)HIDD * HIDD];

// ---------------- helpers ----------------
__device__ __forceinline__ unsigned f2tf(float f) {
    unsigned u;
    asm("cvt.rna.tf32.f32 %0, %1;" : "=r"(u) : "f"(f));
    return u;
}

__device__ __forceinline__ unsigned smem_u32(const void* p) {
    unsigned a;
    asm("{ .reg .u64 t; cvta.to.shared.u64 t, %1; cvt.u32.u64 %0, t; }" : "=r"(a) : "l"(p));
    return a;
}

__device__ __forceinline__ void cp16(unsigned dst, const void* src) {
    asm volatile("cp.async.cg.shared.global [%0], [%1], 16;\n" :: "r"(dst), "l"(src));
}

__device__ __forceinline__ void mma_tf32(float (&c)[4],
                                         unsigned a0, unsigned a1, unsigned a2, unsigned a3,
                                         unsigned b0, unsigned b1) {
    asm volatile(
        "mma.sync.aligned.m16n8k8.row.col.f32.tf32.tf32.f32 "
        "{%0,%1,%2,%3},{%4,%5,%6,%7},{%8,%9},{%0,%1,%2,%3};\n"
        : "+f"(c[0]), "+f"(c[1]), "+f"(c[2]), "+f"(c[3])
        : "r"(a0), "r"(a1), "r"(a2), "r"(a3), "r"(b0), "r"(b1));
}

__device__ __forceinline__ void mma_f16(float (&c)[4],
                                        unsigned a0, unsigned a1, unsigned a2, unsigned a3,
                                        unsigned b0, unsigned b1) {
    asm volatile(
        "mma.sync.aligned.m16n8k16.row.col.f32.f16.f16.f32 "
        "{%0,%1,%2,%3},{%4,%5,%6,%7},{%8,%9},{%0,%1,%2,%3};\n"
        : "+f"(c[0]), "+f"(c[1]), "+f"(c[2]), "+f"(c[3])
        : "r"(a0), "r"(a1), "r"(a2), "r"(a3), "r"(b0), "r"(b1));
}

// ---------------- fp16 GEMM: C[M,N] = A[M,K] * B[N,K]^T (K in halves) ------------
// R9-validated skeleton: block 128x128, 4 warps (2x2), warp tile 64x64, 3-stage
// cp.async pipeline. BK = 64 halves (128B/row, 4 k16-steps/ktile), nk = K/64 = 32.
// smem row stride 36 words (32 data + 4 pad): fragment banks (4g+tg)%32 all-distinct.
// Fragment double-buffering identical to R9. mma = m16n8k16.f16, fp32 accumulate.
#define NSTG 3
#define SRD 36
#define STW (256 * SRD)
#define GEMM_SMEM (NSTG * STW * 4)         // 110592 bytes

__global__ __launch_bounds__(128, 2) void gemm_h(const __half* __restrict__ A,
                                                 const __half* __restrict__ Bm,
                                                 float* __restrict__ C,
                                                 int M, int N, int K) {
    extern __shared__ unsigned smu[];
    const unsigned smb = smem_u32(smu);
    const int tid = threadIdx.x;
    const int lane = tid & 31;
    const int w = tid >> 5;
    const int g = lane >> 2;
    const int tg = lane & 3;
    const int wrow = (w >> 1) * 64;
    const int wcol = (w & 1) * 64;
    const int bm = blockIdx.y * 128;
    const int bn = blockIdx.x * 128;
    const int nk = K >> 6;                 // BK = 64 halves

    float acc[4][8][4];
#pragma unroll
    for (int i = 0; i < 4; i++)
#pragma unroll
        for (int j = 0; j < 8; j++)
#pragma unroll
            for (int l = 0; l < 4; l++) acc[i][j][l] = 0.f;

    // loader: A 128 rows + B 128 rows, 8 x 16B chunks per row; 16 cp16 per thread
#define FILL(slot, ktv)                                                                     \
    {                                                                                       \
        const unsigned stA = smb + (slot) * (STW * 4);                                      \
        const unsigned stB = stA + 128 * SRD * 4;                                           \
        const int kof = (ktv) * 64;                                                         \
        _Pragma("unroll")                                                                   \
        for (int i = 0; i < 8; i++) {                                                       \
            int id = tid + 128 * i;                                                         \
            int r = id >> 3, ch = id & 7;                                                   \
            cp16(stA + (r * SRD + ch * 4) * 4, A + (size_t)(bm + r) * K + kof + ch * 8);    \
            cp16(stB + (r * SRD + ch * 4) * 4, Bm + (size_t)(bn + r) * K + kof + ch * 8);   \
        }                                                                                   \
        asm volatile("cp.async.commit_group;" ::: "memory");                                \
    }

    FILL(0, 0)
    FILL(1, 1)

    for (int kt = 0; kt < nk; kt++) {
        asm volatile("cp.async.wait_group 1;" ::: "memory");
        __syncthreads();
        const int pf = kt + 2;
        if (pf < nk) {
            FILL(pf % 3, pf)
        } else {
            asm volatile("cp.async.commit_group;" ::: "memory");
        }

        const unsigned* sa = smu + (kt % 3) * STW;
        const unsigned* sb = sa + 128 * SRD;

        unsigned af[2][4][4], bf[2][8][2];
#define LOAD_FRAGS(p, ks)                                             \
        {                                                             \
            const int ko = (ks) * 8 + tg;                             \
            _Pragma("unroll")                                         \
            for (int mt = 0; mt < 4; mt++) {                          \
                int r0 = wrow + mt * 16 + g;                          \
                af[p][mt][0] = sa[r0 * SRD + ko];                     \
                af[p][mt][1] = sa[(r0 + 8) * SRD + ko];               \
                af[p][mt][2] = sa[r0 * SRD + ko + 4];                 \
                af[p][mt][3] = sa[(r0 + 8) * SRD + ko + 4];           \
            }                                                         \
            _Pragma("unroll")                                         \
            for (int nt = 0; nt < 8; nt++) {                          \
                int rn = wcol + nt * 8 + g;                           \
                bf[p][nt][0] = sb[rn * SRD + ko];                     \
                bf[p][nt][1] = sb[rn * SRD + ko + 4];                 \
            }                                                         \
        }

        LOAD_FRAGS(0, 0)
#pragma unroll
        for (int ks = 0; ks < 4; ks++) {
            const int cb = ks & 1;
            if (ks < 3) LOAD_FRAGS(cb ^ 1, ks + 1)
#pragma unroll
            for (int mt = 0; mt < 4; mt++)
#pragma unroll
                for (int nt = 0; nt < 8; nt++)
                    mma_f16(acc[mt][nt], af[cb][mt][0], af[cb][mt][1], af[cb][mt][2],
                            af[cb][mt][3], bf[cb][nt][0], bf[cb][nt][1]);
        }
#undef LOAD_FRAGS
    }

#pragma unroll
    for (int mt = 0; mt < 4; mt++) {
        int rr = bm + wrow + mt * 16 + g;
#pragma unroll
        for (int nt = 0; nt < 8; nt++) {
            int cc = bn + wcol + nt * 8 + 2 * tg;
            *(float2*)&C[(size_t)rr * N + cc] = make_float2(acc[mt][nt][0], acc[mt][nt][1]);
            *(float2*)&C[(size_t)(rr + 8) * N + cc] = make_float2(acc[mt][nt][2], acc[mt][nt][3]);
        }
    }
#undef FILL
}

// ---------------- fp32 -> fp16 round (elementwise) ----------------
struct alignas(8) H4 { __half2 a, b; };
__global__ void round_half_kernel(const float4* __restrict__ in, H4* __restrict__ out) {
    int i = blockIdx.x * blockDim.x + threadIdx.x;
    float4 v = in[i];
    H4 o;
    o.a = __floats2half2_rn(v.x, v.y);
    o.b = __floats2half2_rn(v.z, v.w);
    out[i] = o;
}

// ---------------- RoPE + split + transpose (R9 version: plain fp32 out) ----------
__global__ void rope_split_kernel(const float* __restrict__ cosb, const float* __restrict__ sinb) {
    int idx = blockIdx.x * blockDim.x + threadIdx.x;  // pair index, exact grid
    int m = idx / 3072;
    int p = idx - m * 3072;
    int o = p * 2;
    int head = o >> 7;
    int d = o & 127;
    int b = m >> 11;
    int s = m & 2047;
    float2 x = *(const float2*)(g_qkv + (size_t)m * NQKV + o);
    if (head < 2 * HH) {
        float c = cosb[s * DHD + d];
        float sn = sinb[s * DHD + d];
        float y0 = x.x * c - x.y * sn;
        float y1 = x.y * c + x.x * sn;
        if (head < HH) {
            const float sc = 0.08838834764831845f;  // 1/sqrt(128)
            float* dst = g_q + (((size_t)(b * HH + head)) * SS + s) * DHD + d;
            *(float2*)dst = make_float2(y0 * sc, y1 * sc);
        } else {
            float* dst = g_k + (((size_t)(b * HH + head - HH)) * SS + s) * DHD + d;
            *(float2*)dst = make_float2(y0, y1);
        }
    } else {
        float* dst = g_v + (((size_t)(b * HH + head - 2 * HH)) * SS + s) * DHD + d;
        *(float2*)dst = x;
    }
}

// ---------------- Flash attention (R9 measured-best version; epilogue -> fp16) ----------
// Grid: (S/128, B*H). 256 threads = 8 warps, each warp owns 16 q-rows.
// smem (uints): Q[128][132], K[64][132], V[64][136], P[128][68]  -> 171008 bytes
#define FA_SMEM_BYTES 171008

__global__ __launch_bounds__(256, 1) void flash_kernel() {
    extern __shared__ unsigned fsm[];
    unsigned* sQ = fsm;                // 128*132 = 16896
    unsigned* sK = fsm + 16896;        // 64*132  =  8448
    unsigned* sV = fsm + 25344;        // 64*136  =  8704
    unsigned* sP = fsm + 34048;        // 128*68  =  8704

    const int tid = threadIdx.x;
    const int lane = tid & 31;
    const int w = tid >> 5;
    const int g = lane >> 2;
    const int tg = lane & 3;
    const int qt = blockIdx.x;
    const int bh = blockIdx.y;
    const int qrow = w * 16;

    const float* qp = g_q + ((size_t)bh * SS + qt * 128) * DHD;
#pragma unroll
    for (int i = 0; i < 16; i++) {
        int id = tid + 256 * i;
        int r = id >> 5, c4 = (id & 31) * 4;
        float4 v = *(const float4*)(qp + (size_t)r * DHD + c4);
        unsigned* d = sQ + r * 132 + c4;
        d[0] = f2tf(v.x); d[1] = f2tf(v.y); d[2] = f2tf(v.z); d[3] = f2tf(v.w);
    }

    float m0 = -1e30f, m1 = -1e30f, l0 = 0.f, l1 = 0.f;
    float oacc[16][4];
#pragma unroll
    for (int nt = 0; nt < 16; nt++) { oacc[nt][0] = 0; oacc[nt][1] = 0; oacc[nt][2] = 0; oacc[nt][3] = 0; }

    for (int kt = 0; kt < SS / 64; kt++) {
        const float* kp = g_k + ((size_t)bh * SS + kt * 64) * DHD;
        const float* vp = g_v + ((size_t)bh * SS + kt * 64) * DHD;
#pragma unroll
        for (int i = 0; i < 8; i++) {
            int id = tid + 256 * i;
            int r = id >> 5, c4 = (id & 31) * 4;
            float4 kv = *(const float4*)(kp + (size_t)r * DHD + c4);
            unsigned* dk = sK + r * 132 + c4;
            dk[0] = f2tf(kv.x); dk[1] = f2tf(kv.y); dk[2] = f2tf(kv.z); dk[3] = f2tf(kv.w);
            float4 vv = *(const float4*)(vp + (size_t)r * DHD + c4);
            unsigned* dv = sV + r * 136 + c4;
            dv[0] = f2tf(vv.x); dv[1] = f2tf(vv.y); dv[2] = f2tf(vv.z); dv[3] = f2tf(vv.w);
        }
        __syncthreads();

        // S = Q K^T  (scale already folded into Q)
        float sacc[8][4];
#pragma unroll
        for (int nt = 0; nt < 8; nt++) { sacc[nt][0] = 0; sacc[nt][1] = 0; sacc[nt][2] = 0; sacc[nt][3] = 0; }
#pragma unroll
        for (int ks = 0; ks < 16; ks++) {
            unsigned a0 = sQ[(qrow + g) * 132 + ks * 8 + tg];
            unsigned a1 = sQ[(qrow + g + 8) * 132 + ks * 8 + tg];
            unsigned a2 = sQ[(qrow + g) * 132 + ks * 8 + tg + 4];
            unsigned a3 = sQ[(qrow + g + 8) * 132 + ks * 8 + tg + 4];
#pragma unroll
            for (int nt = 0; nt < 8; nt++) {
                unsigned b0 = sK[(nt * 8 + g) * 132 + ks * 8 + tg];
                unsigned b1 = sK[(nt * 8 + g) * 132 + ks * 8 + tg + 4];
                mma_tf32(sacc[nt], a0, a1, a2, a3, b0, b1);
            }
        }

        // online softmax (rows g and g+8 of this warp's 16)
        float mx0 = sacc[0][0], mx1 = sacc[0][2];
#pragma unroll
        for (int nt = 0; nt < 8; nt++) {
            mx0 = fmaxf(mx0, fmaxf(sacc[nt][0], sacc[nt][1]));
            mx1 = fmaxf(mx1, fmaxf(sacc[nt][2], sacc[nt][3]));
        }
        mx0 = fmaxf(mx0, __shfl_xor_sync(0xffffffffu, mx0, 1));
        mx0 = fmaxf(mx0, __shfl_xor_sync(0xffffffffu, mx0, 2));
        mx1 = fmaxf(mx1, __shfl_xor_sync(0xffffffffu, mx1, 1));
        mx1 = fmaxf(mx1, __shfl_xor_sync(0xffffffffu, mx1, 2));
        float nm0 = fmaxf(m0, mx0), nm1 = fmaxf(m1, mx1);
        float al0 = __expf(m0 - nm0), al1 = __expf(m1 - nm1);
        float sum0 = 0.f, sum1 = 0.f;
        unsigned* pr0 = sP + (qrow + g) * 68;
        unsigned* pr1 = sP + (qrow + g + 8) * 68;
#pragma unroll
        for (int nt = 0; nt < 8; nt++) {
            int cc = nt * 8 + 2 * tg;
            unsigned u00 = f2tf(__expf(sacc[nt][0] - nm0));
            unsigned u01 = f2tf(__expf(sacc[nt][1] - nm0));
            unsigned u10 = f2tf(__expf(sacc[nt][2] - nm1));
            unsigned u11 = f2tf(__expf(sacc[nt][3] - nm1));
            sum0 += __uint_as_float(u00) + __uint_as_float(u01);  // sum the tf32-rounded P
            sum1 += __uint_as_float(u10) + __uint_as_float(u11);
            pr0[cc] = u00; pr0[cc + 1] = u01;
            pr1[cc] = u10; pr1[cc + 1] = u11;
        }
        sum0 += __shfl_xor_sync(0xffffffffu, sum0, 1);
        sum0 += __shfl_xor_sync(0xffffffffu, sum0, 2);
        sum1 += __shfl_xor_sync(0xffffffffu, sum1, 1);
        sum1 += __shfl_xor_sync(0xffffffffu, sum1, 2);
        l0 = l0 * al0 + sum0;
        l1 = l1 * al1 + sum1;
        m0 = nm0; m1 = nm1;
#pragma unroll
        for (int nt = 0; nt < 16; nt++) {
            oacc[nt][0] *= al0; oacc[nt][1] *= al0;
            oacc[nt][2] *= al1; oacc[nt][3] *= al1;
        }
        __syncwarp();

        // O += P V   (P is A-operand via smem, V is B-operand; V stride 136 = conflict-free)
#pragma unroll
        for (int ks = 0; ks < 8; ks++) {
            unsigned a0 = sP[(qrow + g) * 68 + ks * 8 + tg];
            unsigned a1 = sP[(qrow + g + 8) * 68 + ks * 8 + tg];
            unsigned a2 = sP[(qrow + g) * 68 + ks * 8 + tg + 4];
            unsigned a3 = sP[(qrow + g + 8) * 68 + ks * 8 + tg + 4];
#pragma unroll
            for (int nt = 0; nt < 16; nt++) {
                unsigned b0 = sV[(ks * 8 + tg) * 136 + nt * 8 + g];
                unsigned b1 = sV[(ks * 8 + tg + 4) * 136 + nt * 8 + g];
                mma_tf32(oacc[nt], a0, a1, a2, a3, b0, b1);
            }
        }
        __syncthreads();
    }

    float inv0 = 1.0f / l0, inv1 = 1.0f / l1;
    int b = bh >> 4, h = bh & 15;
    int srow = qt * 128 + qrow + g;
    __half* op0 = g_attn_h + (((size_t)b * SS + srow) * HH + h) * DHD;
    __half* op1 = op0 + (size_t)8 * HH * DHD;
    // outputs written fp16 (same 10-bit mantissa as tf32) for the fp16 output GEMM
#pragma unroll
    for (int nt = 0; nt < 16; nt++) {
        int cc = nt * 8 + 2 * tg;
        *(__half2*)(op0 + cc) = __floats2half2_rn(oacc[nt][0] * inv0, oacc[nt][1] * inv0);
        *(__half2*)(op1 + cc) = __floats2half2_rn(oacc[nt][2] * inv1, oacc[nt][3] * inv1);
    }
}

// ---------------- launcher ----------------
extern "C" void kernel_launch(void* const* d_in, const int* in_sizes, int n_in,
                              void* d_out, int out_size) {
    const float* hidden = (const float*)d_in[0];
    const float* cosb   = (const float*)d_in[1];
    const float* sinb   = (const float*)d_in[2];
    const float* wqkv   = (const float*)d_in[3];
    const float* wo     = (const float*)d_in[4];

    float* qkv = nullptr;
    __half *attn_h = nullptr, *hid_h = nullptr, *wqkv_h = nullptr, *wo_h = nullptr;
    cudaGetSymbolAddress((void**)&qkv, g_qkv);
    cudaGetSymbolAddress((void**)&attn_h, g_attn_h);
    cudaGetSymbolAddress((void**)&hid_h, g_hid_h);
    cudaGetSymbolAddress((void**)&wqkv_h, g_wqkv_h);
    cudaGetSymbolAddress((void**)&wo_h, g_wo_h);
    cudaFuncSetAttribute(flash_kernel, cudaFuncAttributeMaxDynamicSharedMemorySize, FA_SMEM_BYTES);
    cudaFuncSetAttribute(gemm_h, cudaFuncAttributeMaxDynamicSharedMemorySize, GEMM_SMEM);

    // 0) fp16 conversion of GEMM operands (exact grids: n/4/256 blocks)
    round_half_kernel<<<8192, 256>>>((const float4*)hidden, (H4*)hid_h);     // 8.4M elems
    round_half_kernel<<<12288, 256>>>((const float4*)wqkv, (H4*)wqkv_h);     // 12.6M
    round_half_kernel<<<4096, 256>>>((const float4*)wo, (H4*)wo_h);          // 4.2M

    // 1) QKV projection (fp16 tensor cores): [4096,2048] x [6144,2048]^T -> fp32
    gemm_h<<<dim3(NQKV / 128, (BB * SS) / 128), 128, GEMM_SMEM>>>(hid_h, wqkv_h, qkv, BB * SS, NQKV, HIDD);

    // 2) RoPE + split + transpose (12,582,912 pairs = 49152 * 256 exactly)
    rope_split_kernel<<<49152, 256>>>(cosb, sinb);

    // 3) Attention (tf32 path, unchanged; writes fp16 attn)
    flash_kernel<<<dim3(SS / 128, BB * HH), 256, FA_SMEM_BYTES>>>();

    // 4) Output projection (fp16 tensor cores): [4096,2048] x [2048,2048]^T -> d_out
    gemm_h<<<dim3(HIDD / 128, (BB * SS) / 128), 128, GEMM_SMEM>>>(attn_h, wo_h, (float*)d_out, BB * SS, HIDD, HIDD);
}

// round 17
// speedup vs baseline: 1.7720x; 1.2577x over previous
#include <cuda_runtime.h>
#include <cuda_fp16.h>
#include <math.h>

#define BB 2
#define SS 2048
#define HH 16
#define DHD 128
#define HIDD 2048
#define NQKV 6144   // (H + 2*HKV) * DH

// ---------------- scratch (static device allocations — allowed) ----------------
__device__ float g_qkv[(size_t)BB * SS * NQKV];          // [4096, 6144] fp32 (GEMM1 out)
__device__ __half g_q_h[(size_t)BB * HH * SS * DHD];     // [bh][s][d] fp16, scale folded
__device__ __half g_k_h[(size_t)BB * HH * SS * DHD];     // [bh][s][d] fp16
__device__ __half g_vt_h[(size_t)BB * HH * DHD * SS];    // [bh][d][s] fp16 (transposed V)
__device__ __half g_attn_h[(size_t)BB * SS * HH * DHD];  // [b, s, h, d] fp16 (GEMM2 A)
__device__ __half g_hid_h[(size_t)BB * SS * HIDD];       // fp16 copies of GEMM operands
__device__ __half g_wqkv_h[(size_t)NQKV * HIDD];
__device__ __half g_wo_h[(size_t)HIDD * HIDD];

// ---------------- helpers ----------------
__device__ __forceinline__ unsigned smem_u32(const void* p) {
    unsigned a;
    asm("{ .reg .u64 t; cvta.to.shared.u64 t, %1; cvt.u32.u64 %0, t; }" : "=r"(a) : "l"(p));
    return a;
}

__device__ __forceinline__ void cp16(unsigned dst, const void* src) {
    asm volatile("cp.async.cg.shared.global [%0], [%1], 16;\n" :: "r"(dst), "l"(src));
}

__device__ __forceinline__ void mma_f16(float (&c)[4],
                                        unsigned a0, unsigned a1, unsigned a2, unsigned a3,
                                        unsigned b0, unsigned b1) {
    asm volatile(
        "mma.sync.aligned.m16n8k16.row.col.f32.f16.f16.f32 "
        "{%0,%1,%2,%3},{%4,%5,%6,%7},{%8,%9},{%0,%1,%2,%3};\n"
        : "+f"(c[0]), "+f"(c[1]), "+f"(c[2]), "+f"(c[3])
        : "r"(a0), "r"(a1), "r"(a2), "r"(a3), "r"(b0), "r"(b1));
}

// ---------------- fp16 GEMM (unchanged from R15: measured 353us GEMM1) ------------
#define NSTG 3
#define SRD 36
#define STW (256 * SRD)
#define GEMM_SMEM (NSTG * STW * 4)         // 110592 bytes

__global__ __launch_bounds__(128, 2) void gemm_h(const __half* __restrict__ A,
                                                 const __half* __restrict__ Bm,
                                                 float* __restrict__ C,
                                                 int M, int N, int K) {
    extern __shared__ unsigned smu[];
    const unsigned smb = smem_u32(smu);
    const int tid = threadIdx.x;
    const int lane = tid & 31;
    const int w = tid >> 5;
    const int g = lane >> 2;
    const int tg = lane & 3;
    const int wrow = (w >> 1) * 64;
    const int wcol = (w & 1) * 64;
    const int bm = blockIdx.y * 128;
    const int bn = blockIdx.x * 128;
    const int nk = K >> 6;                 // BK = 64 halves

    float acc[4][8][4];
#pragma unroll
    for (int i = 0; i < 4; i++)
#pragma unroll
        for (int j = 0; j < 8; j++)
#pragma unroll
            for (int l = 0; l < 4; l++) acc[i][j][l] = 0.f;

#define FILL(slot, ktv)                                                                     \
    {                                                                                       \
        const unsigned stA = smb + (slot) * (STW * 4);                                      \
        const unsigned stB = stA + 128 * SRD * 4;                                           \
        const int kof = (ktv) * 64;                                                         \
        _Pragma("unroll")                                                                   \
        for (int i = 0; i < 8; i++) {                                                       \
            int id = tid + 128 * i;                                                         \
            int r = id >> 3, ch = id & 7;                                                   \
            cp16(stA + (r * SRD + ch * 4) * 4, A + (size_t)(bm + r) * K + kof + ch * 8);    \
            cp16(stB + (r * SRD + ch * 4) * 4, Bm + (size_t)(bn + r) * K + kof + ch * 8);   \
        }                                                                                   \
        asm volatile("cp.async.commit_group;" ::: "memory");                                \
    }

    FILL(0, 0)
    FILL(1, 1)

    for (int kt = 0; kt < nk; kt++) {
        asm volatile("cp.async.wait_group 1;" ::: "memory");
        __syncthreads();
        const int pf = kt + 2;
        if (pf < nk) {
            FILL(pf % 3, pf)
        } else {
            asm volatile("cp.async.commit_group;" ::: "memory");
        }

        const unsigned* sa = smu + (kt % 3) * STW;
        const unsigned* sb = sa + 128 * SRD;

        unsigned af[2][4][4], bf[2][8][2];
#define LOAD_FRAGS(p, ks)                                             \
        {                                                             \
            const int ko = (ks) * 8 + tg;                             \
            _Pragma("unroll")                                         \
            for (int mt = 0; mt < 4; mt++) {                          \
                int r0 = wrow + mt * 16 + g;                          \
                af[p][mt][0] = sa[r0 * SRD + ko];                     \
                af[p][mt][1] = sa[(r0 + 8) * SRD + ko];               \
                af[p][mt][2] = sa[r0 * SRD + ko + 4];                 \
                af[p][mt][3] = sa[(r0 + 8) * SRD + ko + 4];           \
            }                                                         \
            _Pragma("unroll")                                         \
            for (int nt = 0; nt < 8; nt++) {                          \
                int rn = wcol + nt * 8 + g;                           \
                bf[p][nt][0] = sb[rn * SRD + ko];                     \
                bf[p][nt][1] = sb[rn * SRD + ko + 4];                 \
            }                                                         \
        }

        LOAD_FRAGS(0, 0)
#pragma unroll
        for (int ks = 0; ks < 4; ks++) {
            const int cb = ks & 1;
            if (ks < 3) LOAD_FRAGS(cb ^ 1, ks + 1)
#pragma unroll
            for (int mt = 0; mt < 4; mt++)
#pragma unroll
                for (int nt = 0; nt < 8; nt++)
                    mma_f16(acc[mt][nt], af[cb][mt][0], af[cb][mt][1], af[cb][mt][2],
                            af[cb][mt][3], bf[cb][nt][0], bf[cb][nt][1]);
        }
#undef LOAD_FRAGS
    }

#pragma unroll
    for (int mt = 0; mt < 4; mt++) {
        int rr = bm + wrow + mt * 16 + g;
#pragma unroll
        for (int nt = 0; nt < 8; nt++) {
            int cc = bn + wcol + nt * 8 + 2 * tg;
            *(float2*)&C[(size_t)rr * N + cc] = make_float2(acc[mt][nt][0], acc[mt][nt][1]);
            *(float2*)&C[(size_t)(rr + 8) * N + cc] = make_float2(acc[mt][nt][2], acc[mt][nt][3]);
        }
    }
#undef FILL
}

// ---------------- fp32 -> fp16 round (elementwise) ----------------
struct alignas(8) H4 { __half2 a, b; };
__global__ void round_half_kernel(const float4* __restrict__ in, H4* __restrict__ out) {
    int i = blockIdx.x * blockDim.x + threadIdx.x;
    float4 v = in[i];
    H4 o;
    o.a = __floats2half2_rn(v.x, v.y);
    o.b = __floats2half2_rn(v.z, v.w);
    out[i] = o;
}

// ---------------- RoPE + split (Q,K only) -> fp16 head-major ----------
__global__ void rope_split_kernel(const float* __restrict__ cosb, const float* __restrict__ sinb) {
    int idx = blockIdx.x * blockDim.x + threadIdx.x;  // 4096*2048 pair-threads exactly
    int m = idx >> 11;          // token 0..4095
    int p = idx & 2047;         // pair within Q+K region
    int o = p * 2;
    int head = o >> 7;          // 0..31
    int d = o & 127;
    int b = m >> 11;
    int s = m & 2047;
    float2 x = *(const float2*)(g_qkv + (size_t)m * NQKV + o);
    float c = cosb[s * DHD + d];
    float sn = sinb[s * DHD + d];
    float y0 = x.x * c - x.y * sn;
    float y1 = x.y * c + x.x * sn;
    if (head < HH) {
        const float sc = 0.08838834764831845f;  // 1/sqrt(128)
        __half* dst = g_q_h + (((size_t)(b * HH + head)) * SS + s) * DHD + d;
        *(__half2*)dst = __floats2half2_rn(y0 * sc, y1 * sc);
    } else {
        __half* dst = g_k_h + (((size_t)(b * HH + head - HH)) * SS + s) * DHD + d;
        *(__half2*)dst = __floats2half2_rn(y0, y1);
    }
}

// ---------------- V transpose: g_qkv V-section [b][s][h][d] -> g_vt_h [bh][d][s] fp16 ---
// Canonical 32x32 tile via smem t[32][33] (both phases conflict-free).
// Grid: (s_tile=64, d_tile=4, bh=32), 256 threads; 1 float4 in, 1 uint2 out per thread.
__global__ void vt_kernel() {
    __shared__ float t[32][33];
    const int tid = threadIdx.x;
    const int stile = blockIdx.x * 32;
    const int dtile = blockIdx.y * 32;
    const int bh = blockIdx.z;
    const int b = bh >> 4, h = bh & 15;

    {
        int r = tid >> 3;          // s-row 0..31
        int c4 = (tid & 7) * 4;    // d-col chunk
        float4 v = *(const float4*)(g_qkv + (size_t)(b * SS + stile + r) * NQKV +
                                    (HH + HH) * DHD + h * DHD + dtile + c4);
        t[r][c4] = v.x; t[r][c4 + 1] = v.y; t[r][c4 + 2] = v.z; t[r][c4 + 3] = v.w;
    }
    __syncthreads();
    {
        int dr = tid >> 3;         // d-row 0..31
        int c4 = (tid & 7) * 4;    // s chunk
        __half2 h0 = __floats2half2_rn(t[c4][dr], t[c4 + 1][dr]);
        __half2 h1 = __floats2half2_rn(t[c4 + 2][dr], t[c4 + 3][dr]);
        H4 o; o.a = h0; o.b = h1;
        *(uint2*)(g_vt_h + ((size_t)(bh * DHD + dtile + dr)) * SS + stile + c4) =
            *(uint2*)&o;
    }
}

// ---------------- Flash attention — full fp16 MMAs ----------------
// Grid: (S/128, B*H). 256 threads = 8 warps, each warp owns 16 q-rows.
// smem words: Q[128][68] @0 | K[64][68] @8704 | VT[128][36] @13056 | P[128][36] @17664
// (word = half2; fragment word ks*8+tg / +4 == validated gemm_h mapping; all access
//  patterns give bank (4g+tg)%32 = permutation -> conflict-free)
#define FA_SMEM_BYTES 89088

__global__ __launch_bounds__(256, 1) void flash_kernel() {
    extern __shared__ unsigned fsm[];
    unsigned* sQ = fsm;            // 8704
    unsigned* sK = fsm + 8704;     // 4352
    unsigned* sVT = fsm + 13056;   // 4608
    unsigned* sP = fsm + 17664;    // 4608

    const int tid = threadIdx.x;
    const int lane = tid & 31;
    const int w = tid >> 5;
    const int g = lane >> 2;
    const int tg = lane & 3;
    const int qt = blockIdx.x;
    const int bh = blockIdx.y;
    const int qrow = w * 16;

    // Q staging: 128 rows x 16 uint4 (8 halves each)
    const __half* qp = g_q_h + ((size_t)bh * SS + qt * 128) * DHD;
#pragma unroll
    for (int i = 0; i < 8; i++) {
        int id = tid + 256 * i;
        int r = id >> 4, c = id & 15;
        *(uint4*)&sQ[r * 68 + 4 * c] = *(const uint4*)(qp + (size_t)r * DHD + 8 * c);
    }

    float m0 = -1e30f, m1 = -1e30f, l0 = 0.f, l1 = 0.f;
    float oacc[16][4];
#pragma unroll
    for (int nt = 0; nt < 16; nt++) { oacc[nt][0] = 0; oacc[nt][1] = 0; oacc[nt][2] = 0; oacc[nt][3] = 0; }

    for (int kt = 0; kt < SS / 64; kt++) {
        const __half* kp = g_k_h + ((size_t)bh * SS + kt * 64) * DHD;
        const __half* vtp = g_vt_h + (size_t)bh * DHD * SS + kt * 64;
#pragma unroll
        for (int i = 0; i < 4; i++) {
            int id = tid + 256 * i;
            int r = id >> 4, c = id & 15;
            *(uint4*)&sK[r * 68 + 4 * c] = *(const uint4*)(kp + (size_t)r * DHD + 8 * c);
            int r2 = id >> 3, c2 = id & 7;
            *(uint4*)&sVT[r2 * 36 + 4 * c2] = *(const uint4*)(vtp + (size_t)r2 * SS + 8 * c2);
        }
        __syncthreads();

        // S = Q K^T (fp16 m16n8k16; scale folded into Q)
        float sacc[8][4];
#pragma unroll
        for (int nt = 0; nt < 8; nt++) { sacc[nt][0] = 0; sacc[nt][1] = 0; sacc[nt][2] = 0; sacc[nt][3] = 0; }
#pragma unroll
        for (int ks = 0; ks < 8; ks++) {
            const int ko = ks * 8 + tg;
            unsigned a0 = sQ[(qrow + g) * 68 + ko];
            unsigned a1 = sQ[(qrow + g + 8) * 68 + ko];
            unsigned a2 = sQ[(qrow + g) * 68 + ko + 4];
            unsigned a3 = sQ[(qrow + g + 8) * 68 + ko + 4];
#pragma unroll
            for (int nt = 0; nt < 8; nt++) {
                unsigned b0 = sK[(nt * 8 + g) * 68 + ko];
                unsigned b1 = sK[(nt * 8 + g) * 68 + ko + 4];
                mma_f16(sacc[nt], a0, a1, a2, a3, b0, b1);
            }
        }

        // online softmax (rows g and g+8 of this warp's 16)
        float mx0 = sacc[0][0], mx1 = sacc[0][2];
#pragma unroll
        for (int nt = 0; nt < 8; nt++) {
            mx0 = fmaxf(mx0, fmaxf(sacc[nt][0], sacc[nt][1]));
            mx1 = fmaxf(mx1, fmaxf(sacc[nt][2], sacc[nt][3]));
        }
        mx0 = fmaxf(mx0, __shfl_xor_sync(0xffffffffu, mx0, 1));
        mx0 = fmaxf(mx0, __shfl_xor_sync(0xffffffffu, mx0, 2));
        mx1 = fmaxf(mx1, __shfl_xor_sync(0xffffffffu, mx1, 1));
        mx1 = fmaxf(mx1, __shfl_xor_sync(0xffffffffu, mx1, 2));
        float nm0 = fmaxf(m0, mx0), nm1 = fmaxf(m1, mx1);
        float al0 = __expf(m0 - nm0), al1 = __expf(m1 - nm1);
        float sum0 = 0.f, sum1 = 0.f;
        unsigned* pr0 = sP + (qrow + g) * 36;
        unsigned* pr1 = sP + (qrow + g + 8) * 36;
#pragma unroll
        for (int nt = 0; nt < 8; nt++) {
            __half2 h0 = __floats2half2_rn(__expf(sacc[nt][0] - nm0), __expf(sacc[nt][1] - nm0));
            __half2 h1 = __floats2half2_rn(__expf(sacc[nt][2] - nm1), __expf(sacc[nt][3] - nm1));
            float2 f0 = __half22float2(h0);   // sum the fp16-rounded P
            float2 f1 = __half22float2(h1);
            sum0 += f0.x + f0.y;
            sum1 += f1.x + f1.y;
            pr0[nt * 4 + tg] = *(unsigned*)&h0;
            pr1[nt * 4 + tg] = *(unsigned*)&h1;
        }
        sum0 += __shfl_xor_sync(0xffffffffu, sum0, 1);
        sum0 += __shfl_xor_sync(0xffffffffu, sum0, 2);
        sum1 += __shfl_xor_sync(0xffffffffu, sum1, 1);
        sum1 += __shfl_xor_sync(0xffffffffu, sum1, 2);
        l0 = l0 * al0 + sum0;
        l1 = l1 * al1 + sum1;
        m0 = nm0; m1 = nm1;
#pragma unroll
        for (int nt = 0; nt < 16; nt++) {
            oacc[nt][0] *= al0; oacc[nt][1] *= al0;
            oacc[nt][2] *= al1; oacc[nt][3] *= al1;
        }
        __syncwarp();   // sP rows are warp-private; cross-lane visibility only

        // O += P V  (P A-operand fp16, V^T B-operand fp16)
#pragma unroll
        for (int ks = 0; ks < 4; ks++) {
            const int ko = ks * 8 + tg;
            unsigned a0 = sP[(qrow + g) * 36 + ko];
            unsigned a1 = sP[(qrow + g + 8) * 36 + ko];
            unsigned a2 = sP[(qrow + g) * 36 + ko + 4];
            unsigned a3 = sP[(qrow + g + 8) * 36 + ko + 4];
#pragma unroll
            for (int nt = 0; nt < 16; nt++) {
                unsigned b0 = sVT[(nt * 8 + g) * 36 + ko];
                unsigned b1 = sVT[(nt * 8 + g) * 36 + ko + 4];
                mma_f16(oacc[nt], a0, a1, a2, a3, b0, b1);
            }
        }
        __syncthreads();   // protect sK/sVT (and sQ on kt=0 ordering) before next staging
    }

    float inv0 = 1.0f / l0, inv1 = 1.0f / l1;
    int b = bh >> 4, h = bh & 15;
    int srow = qt * 128 + qrow + g;
    __half* op0 = g_attn_h + (((size_t)b * SS + srow) * HH + h) * DHD;
    __half* op1 = op0 + (size_t)8 * HH * DHD;
#pragma unroll
    for (int nt = 0; nt < 16; nt++) {
        int cc = nt * 8 + 2 * tg;
        *(__half2*)(op0 + cc) = __floats2half2_rn(oacc[nt][0] * inv0, oacc[nt][1] * inv0);
        *(__half2*)(op1 + cc) = __floats2half2_rn(oacc[nt][2] * inv1, oacc[nt][3] * inv1);
    }
}

// ---------------- launcher ----------------
extern "C" void kernel_launch(void* const* d_in, const int* in_sizes, int n_in,
                              void* d_out, int out_size) {
    const float* hidden = (const float*)d_in[0];
    const float* cosb   = (const float*)d_in[1];
    const float* sinb   = (const float*)d_in[2];
    const float* wqkv   = (const float*)d_in[3];
    const float* wo     = (const float*)d_in[4];

    float* qkv = nullptr;
    __half *attn_h = nullptr, *hid_h = nullptr, *wqkv_h = nullptr, *wo_h = nullptr;
    cudaGetSymbolAddress((void**)&qkv, g_qkv);
    cudaGetSymbolAddress((void**)&attn_h, g_attn_h);
    cudaGetSymbolAddress((void**)&hid_h, g_hid_h);
    cudaGetSymbolAddress((void**)&wqkv_h, g_wqkv_h);
    cudaGetSymbolAddress((void**)&wo_h, g_wo_h);
    cudaFuncSetAttribute(flash_kernel, cudaFuncAttributeMaxDynamicSharedMemorySize, FA_SMEM_BYTES);
    cudaFuncSetAttribute(gemm_h, cudaFuncAttributeMaxDynamicSharedMemorySize, GEMM_SMEM);

    // 0) fp16 conversion of GEMM operands
    round_half_kernel<<<8192, 256>>>((const float4*)hidden, (H4*)hid_h);
    round_half_kernel<<<12288, 256>>>((const float4*)wqkv, (H4*)wqkv_h);
    round_half_kernel<<<4096, 256>>>((const float4*)wo, (H4*)wo_h);

    // 1) QKV projection (fp16 tensor cores) -> fp32 qkv
    gemm_h<<<dim3(NQKV / 128, (BB * SS) / 128), 128, GEMM_SMEM>>>(hid_h, wqkv_h, qkv, BB * SS, NQKV, HIDD);

    // 2a) RoPE Q,K -> fp16 head-major (4096*2048 pair-threads = 32768 * 256)
    rope_split_kernel<<<32768, 256>>>(cosb, sinb);

    // 2b) V transpose -> fp16 [bh][d][s]
    vt_kernel<<<dim3(64, 4, 32), 256>>>();

    // 3) Attention (full fp16 MMAs; writes fp16 attn)
    flash_kernel<<<dim3(SS / 128, BB * HH), 256, FA_SMEM_BYTES>>>();

    // 4) Output projection (fp16 tensor cores) -> d_out
    gemm_h<<<dim3(HIDD / 128, (BB * SS) / 128), 128, GEMM_SMEM>>>(attn_h, wo_h, (float*)d_out, BB * SS, HIDD, HIDD);
}